// round 1
// baseline (speedup 1.0000x reference)
#include <cuda_runtime.h>

#define B_   2
#define N_   131072
#define K_   9
#define P_   4
#define D_   4
#define CI_  8
#define CO_  8
#define NTOT (B_ * N_)   // 262144
#define NPB  64          // n-values per 256-thread block (4 p-lanes each)

typedef unsigned long long u64;

// ---- packed f32x2 helpers (sm_10x dual-FP32 path) ----
__device__ __forceinline__ u64 pk2(float lo, float hi) {
    u64 r; asm("mov.b64 %0, {%1, %2};" : "=l"(r) : "f"(lo), "f"(hi)); return r;
}
__device__ __forceinline__ void upk2(float &lo, float &hi, u64 v) {
    asm("mov.b64 {%0, %1}, %2;" : "=f"(lo), "=f"(hi) : "l"(v));
}
__device__ __forceinline__ u64 fma2(u64 a, u64 b, u64 c) {
    u64 d; asm("fma.rn.f32x2 %0, %1, %2, %3;" : "=l"(d) : "l"(a), "l"(b), "l"(c)); return d;
}
__device__ __forceinline__ u64 mul2(u64 a, u64 b) {
    u64 d; asm("mul.rn.f32x2 %0, %1, %2;" : "=l"(d) : "l"(a), "l"(b)); return d;
}

__global__ __launch_bounds__(256, 2)
void pol_kernel(const float* __restrict__ x,
                const float* __restrict__ dx,
                const float* __restrict__ dy,
                const int*   __restrict__ adj,
                const float* __restrict__ phis,
                const float* __restrict__ dists,
                const float* __restrict__ sigma,
                const float* __restrict__ A,
                float* __restrict__ out)
{
    // A in shared, repacked as [d][c][p][o2] pairs so that the 4 p-lanes of a
    // quad hit 4 distinct 16B chunks inside one 128B span -> conflict-free.
    __shared__ __align__(16) u64 A_sh[D_ * CI_ * P_ * (CO_ / 2)];   // 512 u64 = 4 KB
    __shared__ float s_cos[P_], s_sin[P_], s_q[D_], s_C[D_];
    __shared__ float s_nh;

    const int tid = threadIdx.x;

    for (int i = tid; i < D_ * CI_ * P_ * (CO_ / 2); i += 256) {
        int o2 = i & 3;
        int p  = (i >> 2) & 3;
        int c  = (i >> 4) & 7;
        int d  = (i >> 7);
        int g  = (((p * D_ + d) * CI_ + c) * CO_) + o2 * 2;   // global [p][d][s=0][c][o]
        A_sh[i] = pk2(A[g], A[g + 1]);
    }
    if (tid == 0) {
        float sg  = fmaxf(sigma[0], 1e-10f);
        float is2 = 1.0f / (sg * sg);
        float nh  = -0.5f * is2;
        s_nh = nh;
        float norm = rsqrtf(6.283185307179586f * sg * sg);
        #pragma unroll
        for (int p = 0; p < P_; p++) { s_cos[p] = cosf(phis[p]); s_sin[p] = sinf(phis[p]); }
        #pragma unroll
        for (int d = 0; d < D_; d++) {
            float td = dists[d];
            s_q[d] = td * is2;                    // linear-term coefficient
            s_C[d] = expf(nh * td * td) * norm;   // constant term + normalization
        }
    }
    __syncthreads();

    const int p    = tid & 3;
    const int nsub = tid >> 2;
    const int m    = blockIdx.x * NPB + nsub;     // linear (b,n), exact cover
    const int b    = m >> 17;                     // N_ == 2^17
    const int n    = m & (N_ - 1);

    const float cosp = s_cos[p], sinp = s_sin[p], nh = s_nh;
    const float q0 = s_q[0], q1 = s_q[1], q2 = s_q[2], q3 = s_q[3];

    const float* dxr = dx + (size_t)m * K_;
    const float* dyr = dy + (size_t)m * K_;
    const int*   ar  = adj + (size_t)n * K_;
    const float* xb  = x + (size_t)b * N_ * CI_;

    // t[d][c] accumulators packed along c (pairs)
    u64 t2[D_][CI_ / 2];
    #pragma unroll
    for (int d = 0; d < D_; d++)
        #pragma unroll
        for (int cc = 0; cc < CI_ / 2; cc++) t2[d][cc] = 0ull;

    #pragma unroll
    for (int k = 0; k < K_; k++) {
        float dxk = __ldg(dxr + k);
        float dyk = __ldg(dyr + k);
        int   ai  = __ldg(ar + k);
        const ulonglong2* xr = (const ulonglong2*)(xb + (size_t)ai * CI_);
        ulonglong2 xv0 = xr[0];
        ulonglong2 xv1 = xr[1];

        float a  = nh * fmaf(dyk, dyk, dxk * dxk);       // nh*(dx^2+dy^2)
        float cp = fmaf(dyk, sinp, dxk * cosp);          // radial projection
        float w0 = __expf(fmaf(cp, q0, a));
        float w1 = __expf(fmaf(cp, q1, a));
        float w2 = __expf(fmaf(cp, q2, a));
        float w3 = __expf(fmaf(cp, q3, a));
        u64 wp0 = pk2(w0, w0);
        u64 wp1 = pk2(w1, w1);
        u64 wp2 = pk2(w2, w2);
        u64 wp3 = pk2(w3, w3);

        t2[0][0] = fma2(wp0, xv0.x, t2[0][0]);
        t2[0][1] = fma2(wp0, xv0.y, t2[0][1]);
        t2[0][2] = fma2(wp0, xv1.x, t2[0][2]);
        t2[0][3] = fma2(wp0, xv1.y, t2[0][3]);
        t2[1][0] = fma2(wp1, xv0.x, t2[1][0]);
        t2[1][1] = fma2(wp1, xv0.y, t2[1][1]);
        t2[1][2] = fma2(wp1, xv1.x, t2[1][2]);
        t2[1][3] = fma2(wp1, xv1.y, t2[1][3]);
        t2[2][0] = fma2(wp2, xv0.x, t2[2][0]);
        t2[2][1] = fma2(wp2, xv0.y, t2[2][1]);
        t2[2][2] = fma2(wp2, xv1.x, t2[2][2]);
        t2[2][3] = fma2(wp2, xv1.y, t2[2][3]);
        t2[3][0] = fma2(wp3, xv0.x, t2[3][0]);
        t2[3][1] = fma2(wp3, xv0.y, t2[3][1]);
        t2[3][2] = fma2(wp3, xv1.x, t2[3][2]);
        t2[3][3] = fma2(wp3, xv1.y, t2[3][3]);
    }

    // out[d][o] = C_d * sum_c t[d][c] * A[p][d][c][o]
    float* op = out + (size_t)m * (P_ * D_ * CO_) + (size_t)p * (D_ * CO_);
    #pragma unroll
    for (int d = 0; d < D_; d++) {
        u64 cd = pk2(s_C[d], s_C[d]);
        u64 acc0 = 0ull, acc1 = 0ull, acc2 = 0ull, acc3 = 0ull;
        #pragma unroll
        for (int cc = 0; cc < CI_ / 2; cc++) {
            u64 ts = mul2(t2[d][cc], cd);
            float tl, th;
            upk2(tl, th, ts);
            u64 tb0 = pk2(tl, tl);
            u64 tb1 = pk2(th, th);
            int c0 = cc * 2;
            const ulonglong2* a0 =
                (const ulonglong2*)&A_sh[(((d * CI_ + c0) * P_ + p) << 2)];
            ulonglong2 av0 = a0[0];
            ulonglong2 av1 = a0[1];
            acc0 = fma2(tb0, av0.x, acc0);
            acc1 = fma2(tb0, av0.y, acc1);
            acc2 = fma2(tb0, av1.x, acc2);
            acc3 = fma2(tb0, av1.y, acc3);
            const ulonglong2* a1 =
                (const ulonglong2*)&A_sh[(((d * CI_ + c0 + 1) * P_ + p) << 2)];
            ulonglong2 bv0 = a1[0];
            ulonglong2 bv1 = a1[1];
            acc0 = fma2(tb1, bv0.x, acc0);
            acc1 = fma2(tb1, bv0.y, acc1);
            acc2 = fma2(tb1, bv1.x, acc2);
            acc3 = fma2(tb1, bv1.y, acc3);
        }
        ulonglong2 st0; st0.x = acc0; st0.y = acc1;
        ulonglong2 st1; st1.x = acc2; st1.y = acc3;
        ((ulonglong2*)(op + d * CO_))[0] = st0;
        ((ulonglong2*)(op + d * CO_))[1] = st1;
    }
}

extern "C" void kernel_launch(void* const* d_in, const int* in_sizes, int n_in,
                              void* d_out, int out_size)
{
    const float* x     = (const float*)d_in[0];
    const float* dx    = (const float*)d_in[1];
    const float* dy    = (const float*)d_in[2];
    const int*   adj   = (const int*)d_in[3];
    const float* phis  = (const float*)d_in[4];
    const float* dists = (const float*)d_in[5];
    const float* sigma = (const float*)d_in[6];
    const float* A     = (const float*)d_in[7];
    float* out = (float*)d_out;

    dim3 grid(NTOT / NPB);   // 4096
    pol_kernel<<<grid, 256>>>(x, dx, dy, adj, phis, dists, sigma, A, out);
    (void)in_sizes; (void)n_in; (void)out_size;
}

// round 3
// speedup vs baseline: 1.1889x; 1.1889x over previous
#include <cuda_runtime.h>

#define B_   2
#define N_   131072
#define K_   9
#define P_   4
#define D_   4
#define CI_  8
#define CO_  8
#define NTOT (B_ * N_)   // 262144

typedef unsigned long long u64;

// ---- packed f32x2 helpers ----
__device__ __forceinline__ u64 pk2(float lo, float hi) {
    u64 r; asm("mov.b64 %0, {%1, %2};" : "=l"(r) : "f"(lo), "f"(hi)); return r;
}
__device__ __forceinline__ void upk2(float &lo, float &hi, u64 v) {
    asm("mov.b64 {%0, %1}, %2;" : "=f"(lo), "=f"(hi) : "l"(v));
}
__device__ __forceinline__ u64 fma2(u64 a, u64 b, u64 c) {
    u64 d; asm("fma.rn.f32x2 %0, %1, %2, %3;" : "=l"(d) : "l"(a), "l"(b), "l"(c)); return d;
}
__device__ __forceinline__ u64 mul2(u64 a, u64 b) {
    u64 d; asm("mul.rn.f32x2 %0, %1, %2;" : "=l"(d) : "l"(a), "l"(b)); return d;
}
__device__ __forceinline__ u64 add2(u64 a, u64 b) {
    u64 d; asm("add.rn.f32x2 %0, %1, %2;" : "=l"(d) : "l"(a), "l"(b)); return d;
}

// A staged in shared as 16B chunks: A16[d][j][h][p][ch]
//   c = ch*4 + j   (j = c&3, ch = c>>2)
//   h = o-half (o 0..3 vs 4..7), each chunk = 2 o-pairs (4 floats)
// For fixed (d,j,h) the 8 (p,ch) lanes hit 8 consecutive 16B chunks
// = one 128B span -> conflict-free LDS.128 with broadcast across m4.
__device__ __forceinline__ int a16_idx(int d, int j, int h, int p, int ch) {
    return ((((d * 4 + j) * 2 + h) * P_ + p) * 2 + ch);
}

__global__ __launch_bounds__(256, 3)
void pol_kernel(const float* __restrict__ x,
                const float* __restrict__ dx,
                const float* __restrict__ dy,
                const int*   __restrict__ adj,
                const float* __restrict__ phis,
                const float* __restrict__ dists,
                const float* __restrict__ sigma,
                const float* __restrict__ A,
                float* __restrict__ out)
{
    __shared__ __align__(16) ulonglong2 A16[D_ * 4 * 2 * P_ * 2];   // 256 * 16B = 4 KB
    __shared__ __align__(16) u64 stg[8][32][10];                     // 20 KB store staging
    __shared__ float s_cos[P_], s_sin[P_], s_q[D_], s_C[D_], s_nh;

    const int tid = threadIdx.x;

    // Stage A into shared: one thread per (d,c,p) entry (128 entries)
    for (int i = tid; i < D_ * CI_ * P_; i += 256) {
        int p = i & 3;
        int c = (i >> 2) & 7;
        int d = (i >> 5);
        int j  = c & 3;
        int ch = c >> 2;
        int g = p * (D_ * CI_ * CO_) + d * (CI_ * CO_) + c * CO_;  // A[p][d][0][c][o]
        ulonglong2 h0; h0.x = pk2(A[g + 0], A[g + 1]); h0.y = pk2(A[g + 2], A[g + 3]);
        ulonglong2 h1; h1.x = pk2(A[g + 4], A[g + 5]); h1.y = pk2(A[g + 6], A[g + 7]);
        A16[a16_idx(d, j, 0, p, ch)] = h0;
        A16[a16_idx(d, j, 1, p, ch)] = h1;
    }
    if (tid == 0) {
        float sg  = fmaxf(sigma[0], 1e-10f);
        float is2 = 1.0f / (sg * sg);
        float nh  = -0.5f * is2;
        s_nh = nh;
        float norm = rsqrtf(6.283185307179586f * sg * sg);
        #pragma unroll
        for (int p = 0; p < P_; p++) { s_cos[p] = cosf(phis[p]); s_sin[p] = sinf(phis[p]); }
        #pragma unroll
        for (int d = 0; d < D_; d++) {
            float td = dists[d];
            s_q[d] = td * is2;
            s_C[d] = expf(nh * td * td) * norm;
        }
    }
    __syncthreads();

    const int wid  = tid >> 5;
    const int lane = tid & 31;
    const int m4   = lane >> 3;        // which of the warp's 4 m
    const int p    = (lane >> 1) & 3;  // polar angle index
    const int ch   = lane & 1;         // c-half (c in [ch*4, ch*4+4))

    const int m_w0 = blockIdx.x * 32 + wid * 4;   // warp's first m
    const int m    = m_w0 + m4;
    const int b    = m >> 17;                      // N_ == 2^17
    const int n    = m & (N_ - 1);

    const float cosp = s_cos[p], sinp = s_sin[p], nh = s_nh;
    const float q0 = s_q[0], q1 = s_q[1], q2 = s_q[2], q3 = s_q[3];

    const float* dxr = dx + (size_t)m * K_;
    const float* dyr = dy + (size_t)m * K_;
    const int*   ar  = adj + (size_t)n * K_;
    const float* xb  = x + (size_t)b * N_ * CI_ + ch * 4;   // this lane's c-half

    // t[d] accumulators over this lane's 4 c's, packed in pairs
    u64 t2[D_][2];
    #pragma unroll
    for (int d = 0; d < D_; d++) { t2[d][0] = 0ull; t2[d][1] = 0ull; }

    #pragma unroll
    for (int k = 0; k < K_; k++) {
        float dxk = __ldg(dxr + k);
        float dyk = __ldg(dyr + k);
        int   ai  = __ldg(ar + k);
        float4 xv = __ldg((const float4*)(xb + (size_t)ai * CI_));
        u64 xp0 = pk2(xv.x, xv.y);
        u64 xp1 = pk2(xv.z, xv.w);

        float a  = nh * fmaf(dyk, dyk, dxk * dxk);
        float cp = fmaf(dyk, sinp, dxk * cosp);
        float e0 = __expf(fmaf(cp, q0, a));
        float e1 = __expf(fmaf(cp, q1, a));
        float e2 = __expf(fmaf(cp, q2, a));
        float e3 = __expf(fmaf(cp, q3, a));
        u64 w0 = pk2(e0, e0);
        u64 w1 = pk2(e1, e1);
        u64 w2 = pk2(e2, e2);
        u64 w3 = pk2(e3, e3);

        t2[0][0] = fma2(w0, xp0, t2[0][0]);  t2[0][1] = fma2(w0, xp1, t2[0][1]);
        t2[1][0] = fma2(w1, xp0, t2[1][0]);  t2[1][1] = fma2(w1, xp1, t2[1][1]);
        t2[2][0] = fma2(w2, xp0, t2[2][0]);  t2[2][1] = fma2(w2, xp1, t2[2][1]);
        t2[3][0] = fma2(w3, xp0, t2[3][0]);  t2[3][1] = fma2(w3, xp1, t2[3][1]);
    }

    // Partial contraction over this lane's c-half: acc[d][o2]
    u64 acc[D_][4];
    #pragma unroll
    for (int d = 0; d < D_; d++) {
        u64 cd  = pk2(s_C[d], s_C[d]);
        u64 ts0 = mul2(t2[d][0], cd);
        u64 ts1 = mul2(t2[d][1], cd);
        float f0, f1, f2, f3;
        upk2(f0, f1, ts0);
        upk2(f2, f3, ts1);
        float tc[4] = {f0, f1, f2, f3};
        u64 a0 = 0ull, a1 = 0ull, a2 = 0ull, a3 = 0ull;
        #pragma unroll
        for (int j = 0; j < 4; j++) {
            ulonglong2 e0 = A16[a16_idx(d, j, 0, p, ch)];
            ulonglong2 e1 = A16[a16_idx(d, j, 1, p, ch)];
            u64 tb = pk2(tc[j], tc[j]);
            a0 = fma2(tb, e0.x, a0);
            a1 = fma2(tb, e0.y, a1);
            a2 = fma2(tb, e1.x, a2);
            a3 = fma2(tb, e1.y, a3);
        }
        acc[d][0] = a0; acc[d][1] = a1; acc[d][2] = a2; acc[d][3] = a3;
    }

    // Exchange partials with the partner lane (other c-half).
    // Lane keeps d-half == ch: ch=0 -> d{0,1}, ch=1 -> d{2,3}.
    u64 fin[8];
    #pragma unroll
    for (int jj = 0; jj < 8; jj++) {
        int dk = jj >> 2, o2 = jj & 3;
        u64 s  = ch ? acc[dk][o2]     : acc[2 + dk][o2];   // send the half we don't keep
        u64 r  = __shfl_xor_sync(0xffffffffu, s, 1);
        u64 kv = ch ? acc[2 + dk][o2] : acc[dk][o2];
        fin[jj] = add2(kv, r);
    }

    // Stage to shared (row = lane, pad to 10 u64 -> conflict-free STS.128),
    // then fully coalesced STG.128.
    {
        ulonglong2* row = (ulonglong2*)&stg[wid][lane][0];
        ulonglong2 v0; v0.x = fin[0]; v0.y = fin[1];
        ulonglong2 v1; v1.x = fin[2]; v1.y = fin[3];
        ulonglong2 v2; v2.x = fin[4]; v2.y = fin[5];
        ulonglong2 v3; v3.x = fin[6]; v3.y = fin[7];
        row[0] = v0; row[1] = v1; row[2] = v2; row[3] = v3;
    }
    __syncwarp();

    ulonglong2* outw = (ulonglong2*)(out + (size_t)m_w0 * (P_ * D_ * CO_));
    #pragma unroll
    for (int j = 0; j < 4; j++) {
        int c   = j * 32 + lane;     // 16B-chunk index within warp's 2KB region
        int o   = c >> 2;            // owner staging row (= owner lane)
        int sub = c & 3;
        ulonglong2 v = *(const ulonglong2*)&stg[wid][o][sub * 2];
        outw[c] = v;
    }
}

extern "C" void kernel_launch(void* const* d_in, const int* in_sizes, int n_in,
                              void* d_out, int out_size)
{
    const float* x     = (const float*)d_in[0];
    const float* dx    = (const float*)d_in[1];
    const float* dy    = (const float*)d_in[2];
    const int*   adj   = (const int*)d_in[3];
    const float* phis  = (const float*)d_in[4];
    const float* dists = (const float*)d_in[5];
    const float* sigma = (const float*)d_in[6];
    const float* A     = (const float*)d_in[7];
    float* out = (float*)d_out;

    dim3 grid(NTOT / 32);   // 8192 blocks, each warp handles 4 m
    pol_kernel<<<grid, 256>>>(x, dx, dy, adj, phis, dists, sigma, A, out);
    (void)in_sizes; (void)n_in; (void)out_size;
}

// round 4
// speedup vs baseline: 1.3868x; 1.1665x over previous
#include <cuda_runtime.h>

#define B_   2
#define N_   131072
#define K_   9
#define P_   4
#define D_   4
#define CI_  8
#define CO_  8
#define NTOT (B_ * N_)   // 262144

typedef unsigned long long u64;

// ---- packed f32x2 helpers ----
__device__ __forceinline__ u64 pk2(float lo, float hi) {
    u64 r; asm("mov.b64 %0, {%1, %2};" : "=l"(r) : "f"(lo), "f"(hi)); return r;
}
__device__ __forceinline__ void upk2(float &lo, float &hi, u64 v) {
    asm("mov.b64 {%0, %1}, %2;" : "=f"(lo), "=f"(hi) : "l"(v));
}
__device__ __forceinline__ u64 fma2(u64 a, u64 b, u64 c) {
    u64 d; asm("fma.rn.f32x2 %0, %1, %2, %3;" : "=l"(d) : "l"(a), "l"(b), "l"(c)); return d;
}
__device__ __forceinline__ u64 mul2(u64 a, u64 b) {
    u64 d; asm("mul.rn.f32x2 %0, %1, %2;" : "=l"(d) : "l"(a), "l"(b)); return d;
}
__device__ __forceinline__ u64 add2(u64 a, u64 b) {
    u64 d; asm("add.rn.f32x2 %0, %1, %2;" : "=l"(d) : "l"(a), "l"(b)); return d;
}

// A in shared as 16B chunks: A16[d][j][h][p][ch]; for fixed (d,j,h) the 8
// (p,ch) lanes hit 8 consecutive 16B chunks = one 128B span -> conflict-free.
__device__ __forceinline__ int a16_idx(int d, int j, int h, int p, int ch) {
    return ((((d * 4 + j) * 2 + h) * P_ + p) * 2 + ch);
}

__global__ __launch_bounds__(128, 5)
void pol_kernel(const float* __restrict__ x,
                const float* __restrict__ dx,
                const float* __restrict__ dy,
                const int*   __restrict__ adj,
                const float* __restrict__ phis,
                const float* __restrict__ dists,
                const float* __restrict__ sigma,
                const float* __restrict__ A,
                float* __restrict__ out)
{
    __shared__ __align__(16) ulonglong2 A16[256];        // 4 KB
    __shared__ __align__(16) u64 stg[4][640];            // 20 KB (64 chunks * 10 u64 per warp)
    __shared__ __align__(16) float2 dxy_s[K_][32];       // 2304 B, [k][block-local m]
    __shared__ __align__(8)  int    adj_s[K_][32];       // 1152 B
    __shared__ float s_cos[P_], s_sin[P_], s_q[D_], s_C[D_], s_nh;

    const int tid    = threadIdx.x;
    const int base_m = blockIdx.x * 32;            // block covers 32 m
    const int nb     = base_m & (N_ - 1);

    // ---- stage A: exactly one (d,c,p) entry per thread ----
    {
        int p = tid & 3, c = (tid >> 2) & 7, d = tid >> 5;
        int j = c & 3, ch = c >> 2;
        int g = p * (D_ * CI_ * CO_) + d * (CI_ * CO_) + c * CO_;
        ulonglong2 h0, h1;
        h0.x = pk2(A[g + 0], A[g + 1]); h0.y = pk2(A[g + 2], A[g + 3]);
        h1.x = pk2(A[g + 4], A[g + 5]); h1.y = pk2(A[g + 6], A[g + 7]);
        A16[a16_idx(d, j, 0, p, ch)] = h0;
        A16[a16_idx(d, j, 1, p, ch)] = h1;
    }
    // ---- stage dx/dy/adj transposed: 288 elements = 72 float4/int4 ----
    if (tid < 72) {
        float4 xv = __ldg((const float4*)(dx + (size_t)base_m * K_) + tid);
        float4 yv = __ldg((const float4*)(dy + (size_t)base_m * K_) + tid);
        int4   av = __ldg((const int4*)  (adj + (size_t)nb * K_) + tid);
        int e = tid * 4;
        int ml, k;
        ml = (e+0)/9; k = (e+0)%9; dxy_s[k][ml].x = xv.x; dxy_s[k][ml].y = yv.x; adj_s[k][ml] = av.x;
        ml = (e+1)/9; k = (e+1)%9; dxy_s[k][ml].x = xv.y; dxy_s[k][ml].y = yv.y; adj_s[k][ml] = av.y;
        ml = (e+2)/9; k = (e+2)%9; dxy_s[k][ml].x = xv.z; dxy_s[k][ml].y = yv.z; adj_s[k][ml] = av.z;
        ml = (e+3)/9; k = (e+3)%9; dxy_s[k][ml].x = xv.w; dxy_s[k][ml].y = yv.w; adj_s[k][ml] = av.w;
    }
    if (tid == 0) {
        float sg  = fmaxf(sigma[0], 1e-10f);
        float is2 = 1.0f / (sg * sg);
        float nh  = -0.5f * is2;
        s_nh = nh;
        float norm = rsqrtf(6.283185307179586f * sg * sg);
        #pragma unroll
        for (int p = 0; p < P_; p++) { s_cos[p] = cosf(phis[p]); s_sin[p] = sinf(phis[p]); }
        #pragma unroll
        for (int d = 0; d < D_; d++) {
            float td = dists[d];
            s_q[d] = td * is2;
            s_C[d] = expf(nh * td * td) * norm;
        }
    }
    __syncthreads();

    const int wid  = tid >> 5;
    const int lane = tid & 31;
    const int m4   = lane >> 3;
    const int p    = (lane >> 1) & 3;
    const int ch   = lane & 1;

    const int mlA  = wid * 8 + m4 * 2;        // block-local m of this thread's pair
    const int b    = base_m >> 17;            // uniform per block (N_ = 2^17)

    const float cosp = s_cos[p], sinp = s_sin[p], nh = s_nh;
    const float q0 = s_q[0], q1 = s_q[1], q2 = s_q[2], q3 = s_q[3];

    const float* xb = x + (size_t)b * N_ * CI_ + ch * 4;

    u64 tA[D_][2], tB[D_][2];
    #pragma unroll
    for (int d = 0; d < D_; d++) {
        tA[d][0] = 0ull; tA[d][1] = 0ull;
        tB[d][0] = 0ull; tB[d][1] = 0ull;
    }

    #pragma unroll 3
    for (int k = 0; k < K_; k++) {
        float4 dd = *(const float4*)&dxy_s[k][mlA];      // dxA,dyA,dxB,dyB
        int2   aa = *(const int2*)&adj_s[k][mlA];
        float4 xa  = __ldg((const float4*)(xb + (size_t)aa.x * CI_));
        float4 xvb = __ldg((const float4*)(xb + (size_t)aa.y * CI_));

        float ra = nh * fmaf(dd.y, dd.y, dd.x * dd.x);
        float ca = fmaf(dd.y, sinp, dd.x * cosp);
        float rb = nh * fmaf(dd.w, dd.w, dd.z * dd.z);
        float cb = fmaf(dd.w, sinp, dd.z * cosp);

        float eA0 = __expf(fmaf(ca, q0, ra));
        float eA1 = __expf(fmaf(ca, q1, ra));
        float eA2 = __expf(fmaf(ca, q2, ra));
        float eA3 = __expf(fmaf(ca, q3, ra));
        float eB0 = __expf(fmaf(cb, q0, rb));
        float eB1 = __expf(fmaf(cb, q1, rb));
        float eB2 = __expf(fmaf(cb, q2, rb));
        float eB3 = __expf(fmaf(cb, q3, rb));

        u64 xa0 = pk2(xa.x, xa.y),   xa1 = pk2(xa.z, xa.w);
        u64 xb0 = pk2(xvb.x, xvb.y), xb1 = pk2(xvb.z, xvb.w);

        u64 w;
        w = pk2(eA0, eA0); tA[0][0] = fma2(w, xa0, tA[0][0]); tA[0][1] = fma2(w, xa1, tA[0][1]);
        w = pk2(eA1, eA1); tA[1][0] = fma2(w, xa0, tA[1][0]); tA[1][1] = fma2(w, xa1, tA[1][1]);
        w = pk2(eA2, eA2); tA[2][0] = fma2(w, xa0, tA[2][0]); tA[2][1] = fma2(w, xa1, tA[2][1]);
        w = pk2(eA3, eA3); tA[3][0] = fma2(w, xa0, tA[3][0]); tA[3][1] = fma2(w, xa1, tA[3][1]);
        w = pk2(eB0, eB0); tB[0][0] = fma2(w, xb0, tB[0][0]); tB[0][1] = fma2(w, xb1, tB[0][1]);
        w = pk2(eB1, eB1); tB[1][0] = fma2(w, xb0, tB[1][0]); tB[1][1] = fma2(w, xb1, tB[1][1]);
        w = pk2(eB2, eB2); tB[2][0] = fma2(w, xb0, tB[2][0]); tB[2][1] = fma2(w, xb1, tB[2][1]);
        w = pk2(eB3, eB3); tB[3][0] = fma2(w, xb0, tB[3][0]); tB[3][1] = fma2(w, xb1, tB[3][1]);
    }

    // ---- contraction, d processed in pairs (dk, dk+2); A-LDS shared by both m ----
    u64* stg_w = stg[wid];
    #pragma unroll
    for (int dk = 0; dk < 2; dk++) {
        const int d0 = dk, d1 = dk + 2;
        u64 cd0 = pk2(s_C[d0], s_C[d0]);
        u64 cd1 = pk2(s_C[d1], s_C[d1]);

        float tA0[4], tA1[4], tB0[4], tB1[4];
        { u64 v;
          v = mul2(tA[d0][0], cd0); upk2(tA0[0], tA0[1], v);
          v = mul2(tA[d0][1], cd0); upk2(tA0[2], tA0[3], v);
          v = mul2(tA[d1][0], cd1); upk2(tA1[0], tA1[1], v);
          v = mul2(tA[d1][1], cd1); upk2(tA1[2], tA1[3], v);
          v = mul2(tB[d0][0], cd0); upk2(tB0[0], tB0[1], v);
          v = mul2(tB[d0][1], cd0); upk2(tB0[2], tB0[3], v);
          v = mul2(tB[d1][0], cd1); upk2(tB1[0], tB1[1], v);
          v = mul2(tB[d1][1], cd1); upk2(tB1[2], tB1[3], v);
        }

        u64 aA0[4] = {0,0,0,0}, aA1[4] = {0,0,0,0};
        u64 aB0[4] = {0,0,0,0}, aB1[4] = {0,0,0,0};
        #pragma unroll
        for (int j = 0; j < 4; j++) {
            ulonglong2 e0 = A16[a16_idx(d0, j, 0, p, ch)];
            ulonglong2 e1 = A16[a16_idx(d0, j, 1, p, ch)];
            u64 t_;
            t_ = pk2(tA0[j], tA0[j]);
            aA0[0] = fma2(t_, e0.x, aA0[0]); aA0[1] = fma2(t_, e0.y, aA0[1]);
            aA0[2] = fma2(t_, e1.x, aA0[2]); aA0[3] = fma2(t_, e1.y, aA0[3]);
            t_ = pk2(tB0[j], tB0[j]);
            aB0[0] = fma2(t_, e0.x, aB0[0]); aB0[1] = fma2(t_, e0.y, aB0[1]);
            aB0[2] = fma2(t_, e1.x, aB0[2]); aB0[3] = fma2(t_, e1.y, aB0[3]);

            ulonglong2 f0 = A16[a16_idx(d1, j, 0, p, ch)];
            ulonglong2 f1 = A16[a16_idx(d1, j, 1, p, ch)];
            t_ = pk2(tA1[j], tA1[j]);
            aA1[0] = fma2(t_, f0.x, aA1[0]); aA1[1] = fma2(t_, f0.y, aA1[1]);
            aA1[2] = fma2(t_, f1.x, aA1[2]); aA1[3] = fma2(t_, f1.y, aA1[3]);
            t_ = pk2(tB1[j], tB1[j]);
            aB1[0] = fma2(t_, f0.x, aB1[0]); aB1[1] = fma2(t_, f0.y, aB1[1]);
            aB1[2] = fma2(t_, f1.x, aB1[2]); aB1[3] = fma2(t_, f1.y, aB1[3]);
        }

        // exchange with partner lane (other c-half). Keeper of d: ch == d>>1.
        // ch=0 keeps d0 (=dk), ch=1 keeps d1 (=dk+2): kept d = dk + 2*ch.
        u64 finA[4], finB[4];
        #pragma unroll
        for (int o2 = 0; o2 < 4; o2++) {
            u64 sA = ch ? aA0[o2] : aA1[o2];
            u64 rA = __shfl_xor_sync(0xffffffffu, sA, 1);
            u64 kA = ch ? aA1[o2] : aA0[o2];
            finA[o2] = add2(kA, rA);
            u64 sB = ch ? aB0[o2] : aB1[o2];
            u64 rB = __shfl_xor_sync(0xffffffffu, sB, 1);
            u64 kB = ch ? aB1[o2] : aB0[o2];
            finB[o2] = add2(kB, rB);
        }

        // stage: chunk C = m_local*8 + p*2 + ch (m_local in 0..7 warp-local),
        // u64 offset within chunk = dk*4 + o2; chunk stride 10 u64 (padded).
        const int CA = (m4 * 2) * 8 + p * 2 + ch;
        const int CB = CA + 8;
        ulonglong2 v;
        v.x = finA[0]; v.y = finA[1]; *(ulonglong2*)&stg_w[CA * 10 + dk * 4]     = v;
        v.x = finA[2]; v.y = finA[3]; *(ulonglong2*)&stg_w[CA * 10 + dk * 4 + 2] = v;
        v.x = finB[0]; v.y = finB[1]; *(ulonglong2*)&stg_w[CB * 10 + dk * 4]     = v;
        v.x = finB[2]; v.y = finB[3]; *(ulonglong2*)&stg_w[CB * 10 + dk * 4 + 2] = v;
    }
    __syncwarp();

    // fully coalesced store of the warp's 4 KB output region
    ulonglong2* outw = (ulonglong2*)(out + (size_t)(base_m + wid * 8) * (P_ * D_ * CO_));
    #pragma unroll
    for (int t = 0; t < 8; t++) {
        int cc  = t * 32 + lane;                       // 16B chunk index, 0..255
        int off = (cc >> 2) * 10 + (cc & 3) * 2;       // padded stg offset (u64)
        ulonglong2 v = *(const ulonglong2*)&stg_w[off];
        outw[cc] = v;
    }
}

extern "C" void kernel_launch(void* const* d_in, const int* in_sizes, int n_in,
                              void* d_out, int out_size)
{
    const float* x     = (const float*)d_in[0];
    const float* dx    = (const float*)d_in[1];
    const float* dy    = (const float*)d_in[2];
    const int*   adj   = (const int*)d_in[3];
    const float* phis  = (const float*)d_in[4];
    const float* dists = (const float*)d_in[5];
    const float* sigma = (const float*)d_in[6];
    const float* A     = (const float*)d_in[7];
    float* out = (float*)d_out;

    dim3 grid(NTOT / 32);   // 8192 blocks, 128 threads, each thread 2 m
    pol_kernel<<<grid, 128>>>(x, dx, dy, adj, phis, dists, sigma, A, out);
    (void)in_sizes; (void)n_in; (void)out_size;
}